// round 3
// baseline (speedup 1.0000x reference)
#include <cuda_runtime.h>
#include <cstdint>

// TaylorMap: out = x + poly3(x) @ W
//   x : [262144, 16] f32,  W : [969, 16] f32,  out : [262144, 16] f32
//
// Feature ordering (matches reference _poly):
//   row 0          : 1
//   rows 1..16     : x_i
//   rows 17..152   : x_a * x_b   (a>=b)     -> 17 + a(a+1)/2 + b
//   rows 153..968  : x_i*x_a*x_b (i>=a>=b)  -> 153 + C(ii+2,3) + a(a+1)/2 + b
//
// This round: 1 row x 16 cols per thread-iteration.
//  - f32x2 packing axis = output columns; W read as contiguous u64 from smem.
//  - X kept PRE-DUPLICATED (Xd[i] = {x_i,x_i}) so monomials come out of f2mul
//    already lane-duplicated: zero per-apply dup MOVs.
//  - 3 CTAs/SM (<=84 regs), persistent warp-strided loop over 32-row chunks,
//    heavy warps rotated across SMSPs to kill wave-quantization imbalance.

#define NF 16
#define NPOLY 969
#define BLOCK 256
#define GRID 444                 // 3 CTAs/SM x 148 SMs
#define NBATCH 262144
#define NCHUNK (NBATCH / 32)     // 8192 chunks of 32 rows (1 row per lane)
#define NWARPS (GRID * 8)        // 3552 warps

typedef unsigned long long u64;

__device__ __forceinline__ u64 pk2(float lo, float hi) {
    u64 r; asm("mov.b64 %0, {%1, %2};" : "=l"(r) : "f"(lo), "f"(hi)); return r;
}
__device__ __forceinline__ void upk2(u64 v, float& lo, float& hi) {
    asm("mov.b64 {%0, %1}, %2;" : "=f"(lo), "=f"(hi) : "l"(v));
}
__device__ __forceinline__ u64 f2fma(u64 a, u64 b, u64 c) {
    u64 d; asm("fma.rn.f32x2 %0, %1, %2, %3;" : "=l"(d) : "l"(a), "l"(b), "l"(c)); return d;
}
__device__ __forceinline__ u64 f2mul(u64 a, u64 b) {
    u64 d; asm("mul.rn.f32x2 %0, %1, %2;" : "=l"(d) : "l"(a), "l"(b)); return d;
}
__device__ __forceinline__ u64 f2add(u64 a, u64 b) {
    u64 d; asm("add.rn.f32x2 %0, %1, %2;" : "=l"(d) : "l"(a), "l"(b)); return d;
}

#define SMEM_BYTES (NPOLY * NF * 4)   // 62,016 B: scalar W

__global__ void __launch_bounds__(BLOCK, 3)
taylor_kernel(const float* __restrict__ x, const float* __restrict__ W,
              float* __restrict__ out)
{
    extern __shared__ unsigned char smem_raw[];
    float* sW = reinterpret_cast<float*>(smem_raw);

    const int tid = threadIdx.x;

    // cooperative W load (verbatim)
    #pragma unroll 1
    for (int e = tid; e < NPOLY * NF; e += BLOCK) sW[e] = W[e];
    __syncthreads();

    const int wid  = tid >> 5;
    const int lane = tid & 31;
    // Rotate warp index by CTA so the "extra chunk" warps spread across SMSPs.
    const int ew = (wid + (int)blockIdx.x) & 7;
    const int gw = ew * GRID + (int)blockIdx.x;   // 0..NWARPS-1

    const char* wbase = reinterpret_cast<const char*>(sW);

    #pragma unroll 1
    for (int ch = gw; ch < NCHUNK; ch += NWARPS) {
        const long long row = (long long)ch * 32 + lane;

        // ---- load x row (coalesced: lanes = consecutive rows) ----
        const float4* xv = reinterpret_cast<const float4*>(x + row * NF);
        float4 v0 = xv[0], v1 = xv[1], v2 = xv[2], v3 = xv[3];
        float xs[NF] = { v0.x, v0.y, v0.z, v0.w,  v1.x, v1.y, v1.z, v1.w,
                         v2.x, v2.y, v2.z, v2.w,  v3.x, v3.y, v3.z, v3.w };

        // pre-duplicated X: monomial products come out lane-duplicated
        u64 Xd[NF];
        #pragma unroll
        for (int i = 0; i < NF; i++) Xd[i] = pk2(xs[i], xs[i]);

        // ---- acc[c] = cols (2c, 2c+1); init = x (identity) + W[0] (const) ----
        u64 acc[8];
        {
            const ulonglong2* wp = reinterpret_cast<const ulonglong2*>(wbase);
            ulonglong2 a = wp[0], b = wp[1], c2 = wp[2], d = wp[3];
            acc[0] = f2add(pk2(xs[0],  xs[1]),  a.x);
            acc[1] = f2add(pk2(xs[2],  xs[3]),  a.y);
            acc[2] = f2add(pk2(xs[4],  xs[5]),  b.x);
            acc[3] = f2add(pk2(xs[6],  xs[7]),  b.y);
            acc[4] = f2add(pk2(xs[8],  xs[9]),  c2.x);
            acc[5] = f2add(pk2(xs[10], xs[11]), c2.y);
            acc[6] = f2add(pk2(xs[12], xs[13]), d.x);
            acc[7] = f2add(pk2(xs[14], xs[15]), d.y);
        }

        // Apply one feature row: m is the lane-duplicated monomial value
        #define APPLY(ridx, m) do {                                              \
            const ulonglong2* wp =                                               \
                reinterpret_cast<const ulonglong2*>(wbase + (ridx) * 64);        \
            ulonglong2 a = wp[0], b = wp[1], c2 = wp[2], d = wp[3];              \
            acc[0] = f2fma((m), a.x,  acc[0]);  acc[1] = f2fma((m), a.y,  acc[1]);\
            acc[2] = f2fma((m), b.x,  acc[2]);  acc[3] = f2fma((m), b.y,  acc[3]);\
            acc[4] = f2fma((m), c2.x, acc[4]);  acc[5] = f2fma((m), c2.y, acc[5]);\
            acc[6] = f2fma((m), d.x,  acc[6]);  acc[7] = f2fma((m), d.y,  acc[7]);\
        } while (0)

        // degree 1
        #pragma unroll
        for (int i = 0; i < NF; i++) APPLY(1 + i, Xd[i]);

        // degree 2 & 3 fused: p = x_a*x_b (a>=b); q = x_i*p (i>=a)
        #pragma unroll
        for (int ia = 0; ia < NF; ia++) {
            #pragma unroll
            for (int ib = 0; ib <= ia; ib++) {
                u64 p = f2mul(Xd[ia], Xd[ib]);
                APPLY(17 + (ia * (ia + 1)) / 2 + ib, p);
                #pragma unroll
                for (int ii = ia; ii < NF; ii++) {
                    u64 q = f2mul(Xd[ii], p);
                    const int row3 = 153 + (ii * (ii + 1) * (ii + 2)) / 6
                                   + (ia * (ia + 1)) / 2 + ib;
                    APPLY(row3, q);
                }
            }
        }
        #undef APPLY

        // ---- store 16 cols (4 x STG.128, coalesced across lanes) ----
        ulonglong2* op = reinterpret_cast<ulonglong2*>(out + row * NF);
        ulonglong2 s0; s0.x = acc[0]; s0.y = acc[1];
        ulonglong2 s1; s1.x = acc[2]; s1.y = acc[3];
        ulonglong2 s2; s2.x = acc[4]; s2.y = acc[5];
        ulonglong2 s3; s3.x = acc[6]; s3.y = acc[7];
        op[0] = s0; op[1] = s1; op[2] = s2; op[3] = s3;
    }
}

extern "C" void kernel_launch(void* const* d_in, const int* in_sizes, int n_in,
                              void* d_out, int out_size)
{
    const float* x = (const float*)d_in[0];   // [262144, 16]
    const float* W = (const float*)d_in[1];   // [969, 16]
    float* out = (float*)d_out;

    cudaFuncSetAttribute(taylor_kernel,
                         cudaFuncAttributeMaxDynamicSharedMemorySize,
                         SMEM_BYTES);

    taylor_kernel<<<GRID, BLOCK, SMEM_BYTES>>>(x, W, out);
}

// round 4
// speedup vs baseline: 1.0647x; 1.0647x over previous
#include <cuda_runtime.h>
#include <cstdint>

// TaylorMap: out = x + poly3(x) @ W
//   x : [262144, 16] f32,  W : [969, 16] f32,  out : [262144, 16] f32
//
// Feature ordering (matches reference _poly):
//   row 0          : 1
//   rows 1..16     : x_i          (identity residual folded into these rows)
//   rows 17..152   : x_a * x_b   (a>=b)     -> 17 + a(a+1)/2 + b
//   rows 153..968  : x_i*x_a*x_b (i>=a>=b)  -> 153 + C(ii+2,3) + a(a+1)/2 + b
//
// R4: R2's proven 4-row x 8-col thread tile (best LDS:FMA ratio, 2B W per
// FFMA2) + BLOCK=128 @ 3 CTAs/SM for a 170-register budget so ptxas can
// hoist/pipeline the W shared loads (R2 was stuck at 128 regs -> no hoisting,
// fma pipe 40%). Work distributed by atomic ticket (64-row chunks) for
// near-perfect balance; ticket reset by a tiny pre-kernel each launch.

#define NF 16
#define NPOLY 969
#define BLOCK 128
#define GRID 444                 // 3 CTAs/SM x 148 SMs
#define NBATCH 262144
#define CHUNK_ROWS 64            // per warp-ticket: 16 row-groups x 4 rows
#define NCHUNK (NBATCH / CHUNK_ROWS)   // 4096

typedef unsigned long long u64;

__device__ unsigned int g_ticket;

__global__ void reset_ticket_kernel() { g_ticket = 0u; }

__device__ __forceinline__ u64 pk2(float lo, float hi) {
    u64 r; asm("mov.b64 %0, {%1, %2};" : "=l"(r) : "f"(lo), "f"(hi)); return r;
}
__device__ __forceinline__ void upk2(u64 v, float& lo, float& hi) {
    asm("mov.b64 {%0, %1}, %2;" : "=f"(lo), "=f"(hi) : "l"(v));
}
__device__ __forceinline__ float lo2(u64 v) { float a, b; upk2(v, a, b); return a; }
__device__ __forceinline__ float hi2(u64 v) { float a, b; upk2(v, a, b); return b; }
__device__ __forceinline__ u64 dup_lo(u64 v) { float a = lo2(v); return pk2(a, a); }
__device__ __forceinline__ u64 dup_hi(u64 v) { float a = hi2(v); return pk2(a, a); }

__device__ __forceinline__ u64 f2fma(u64 a, u64 b, u64 c) {
    u64 d; asm("fma.rn.f32x2 %0, %1, %2, %3;" : "=l"(d) : "l"(a), "l"(b), "l"(c)); return d;
}
__device__ __forceinline__ u64 f2mul(u64 a, u64 b) {
    u64 d; asm("mul.rn.f32x2 %0, %1, %2;" : "=l"(d) : "l"(a), "l"(b)); return d;
}

#define SMEM_BYTES (NPOLY * NF * 4)   // 62,016 B: scalar W (identity folded)

__global__ void __launch_bounds__(BLOCK, 3)
taylor_kernel(const float* __restrict__ x, const float* __restrict__ W,
              float* __restrict__ out)
{
    extern __shared__ unsigned char smem_raw[];
    float* sW = reinterpret_cast<float*>(smem_raw);

    const int tid = threadIdx.x;

    // Cooperative W load; fold identity residual into deg-1 rows:
    // out = x + poly@W  ==  poly@W'  with  W'[1+i][i] = W[1+i][i] + 1.
    #pragma unroll 1
    for (int e = tid; e < NPOLY * NF; e += BLOCK) {
        float w = W[e];
        int row = e >> 4, col = e & 15;
        if (row - 1 == col) w += 1.0f;
        sW[e] = w;
    }
    __syncthreads();

    const int lane = tid & 31;
    const int cg   = lane & 1;        // column half: cols [8cg, 8cg+8)
    const int rg   = lane >> 1;       // row-group within chunk: 0..15

    const char* wrow_base = reinterpret_cast<const char*>(sW) + cg * 32;

    for (;;) {
        // ---- warp grabs a 64-row chunk ticket ----
        unsigned int t;
        if (lane == 0) t = atomicAdd(&g_ticket, 1u);
        t = __shfl_sync(0xffffffffu, t, 0);
        if (t >= NCHUNK) break;

        const long long rbase = (long long)t * CHUNK_ROWS + rg * 4;

        // ---- load 4 rows of x, pack as row-pairs ----
        const float4* xv = reinterpret_cast<const float4*>(x + rbase * NF);
        u64 xx01[NF], xx23[NF];
        #pragma unroll
        for (int q = 0; q < 4; q++) {
            float4 a = xv[q];          // row 0
            float4 b = xv[4 + q];      // row 1
            float4 c = xv[8 + q];      // row 2
            float4 d = xv[12 + q];     // row 3
            xx01[q * 4 + 0] = pk2(a.x, b.x);  xx23[q * 4 + 0] = pk2(c.x, d.x);
            xx01[q * 4 + 1] = pk2(a.y, b.y);  xx23[q * 4 + 1] = pk2(c.y, d.y);
            xx01[q * 4 + 2] = pk2(a.z, b.z);  xx23[q * 4 + 2] = pk2(c.z, d.z);
            xx01[q * 4 + 3] = pk2(a.w, b.w);  xx23[q * 4 + 3] = pk2(c.w, d.w);
        }

        // ---- acc[r*4 + c] = output cols (8cg+2c, 8cg+2c+1) of row r ----
        u64 acc[16];
        {   // degree-0 init: acc = W'[0][cols]  (identity lives in W' deg-1 rows)
            const ulonglong2* wp = reinterpret_cast<const ulonglong2*>(wrow_base);
            ulonglong2 w0 = wp[0], w1 = wp[1];
            #pragma unroll
            for (int r = 0; r < 4; r++) {
                acc[r * 4 + 0] = w0.x; acc[r * 4 + 1] = w0.y;
                acc[r * 4 + 2] = w1.x; acc[r * 4 + 3] = w1.y;
            }
        }

        #define APPLY(ridx, m01, m23) do {                                          \
            u64 d0 = dup_lo(m01), d1 = dup_hi(m01);                                 \
            u64 d2 = dup_lo(m23), d3 = dup_hi(m23);                                 \
            const ulonglong2* wp =                                                  \
                reinterpret_cast<const ulonglong2*>(wrow_base + (ridx) * 64);       \
            ulonglong2 w0 = wp[0], w1 = wp[1];                                      \
            acc[0]  = f2fma(d0, w0.x, acc[0]);  acc[1]  = f2fma(d0, w0.y, acc[1]);  \
            acc[2]  = f2fma(d0, w1.x, acc[2]);  acc[3]  = f2fma(d0, w1.y, acc[3]);  \
            acc[4]  = f2fma(d1, w0.x, acc[4]);  acc[5]  = f2fma(d1, w0.y, acc[5]);  \
            acc[6]  = f2fma(d1, w1.x, acc[6]);  acc[7]  = f2fma(d1, w1.y, acc[7]);  \
            acc[8]  = f2fma(d2, w0.x, acc[8]);  acc[9]  = f2fma(d2, w0.y, acc[9]);  \
            acc[10] = f2fma(d2, w1.x, acc[10]); acc[11] = f2fma(d2, w1.y, acc[11]); \
            acc[12] = f2fma(d3, w0.x, acc[12]); acc[13] = f2fma(d3, w0.y, acc[13]); \
            acc[14] = f2fma(d3, w1.x, acc[14]); acc[15] = f2fma(d3, w1.y, acc[15]); \
        } while (0)

        // degree 1 (identity already folded into W')
        #pragma unroll
        for (int i = 0; i < NF; i++) {
            APPLY(1 + i, xx01[i], xx23[i]);
        }

        // degree 2 & 3 fused: p = x_a*x_b (a>=b); q = x_i*p (i>=a)
        #pragma unroll
        for (int ia = 0; ia < NF; ia++) {
            #pragma unroll
            for (int ib = 0; ib <= ia; ib++) {
                u64 p01 = f2mul(xx01[ia], xx01[ib]);
                u64 p23 = f2mul(xx23[ia], xx23[ib]);
                APPLY(17 + (ia * (ia + 1)) / 2 + ib, p01, p23);
                #pragma unroll
                for (int ii = ia; ii < NF; ii++) {
                    u64 q01 = f2mul(xx01[ii], p01);
                    u64 q23 = f2mul(xx23[ii], p23);
                    const int row3 = 153 + (ii * (ii + 1) * (ii + 2)) / 6
                                   + (ia * (ia + 1)) / 2 + ib;
                    APPLY(row3, q01, q23);
                }
            }
        }
        #undef APPLY

        // ---- store 4 rows x 8 cols ----
        #pragma unroll
        for (int r = 0; r < 4; r++) {
            ulonglong2 s0; s0.x = acc[r * 4 + 0]; s0.y = acc[r * 4 + 1];
            ulonglong2 s1; s1.x = acc[r * 4 + 2]; s1.y = acc[r * 4 + 3];
            ulonglong2* op =
                reinterpret_cast<ulonglong2*>(out + (rbase + r) * NF + 8 * cg);
            op[0] = s0;
            op[1] = s1;
        }
    }
}

extern "C" void kernel_launch(void* const* d_in, const int* in_sizes, int n_in,
                              void* d_out, int out_size)
{
    const float* x = (const float*)d_in[0];   // [262144, 16]
    const float* W = (const float*)d_in[1];   // [969, 16]
    float* out = (float*)d_out;

    cudaFuncSetAttribute(taylor_kernel,
                         cudaFuncAttributeMaxDynamicSharedMemorySize,
                         SMEM_BYTES);

    reset_ticket_kernel<<<1, 1>>>();
    taylor_kernel<<<GRID, BLOCK, SMEM_BYTES>>>(x, W, out);
}

// round 5
// speedup vs baseline: 1.4966x; 1.4057x over previous
#include <cuda_runtime.h>
#include <cstdint>

// TaylorMap: out = x + poly3(x) @ W
//   x : [262144, 16] f32,  W : [969, 16] f32,  out : [262144, 16] f32
//
// Feature ordering (matches reference _poly):
//   row 0          : 1
//   rows 1..16     : x_i          (identity residual folded into these rows)
//   rows 17..152   : x_a * x_b   (a>=b)     -> 17 + a(a+1)/2 + b
//   rows 153..968  : x_i*x_a*x_b (i>=a>=b)  -> 153 + C(ii+2,3) + a(a+1)/2 + b
//
// R5: CTA-level column split. Each CTA owns 8 of the 16 output columns, so
// its W slice is 31KB -> 3 CTAs/SM (6 warps/SMSP, vs R2's 4) at an 85-reg
// cap with only ~66 regs of thread state (2-row x 8-col tile) -> ptxas has
// headroom to hoist the (now fully warp-uniform) W shared loads.
// Row chunks dispatched by per-half atomic tickets.

#define NF 16
#define NPOLY 969
#define BLOCK 256
#define GRID 444                 // 3 CTAs/SM x 148 SMs; 222 CTAs per col-half
#define NBATCH 262144
#define CHUNK_ROWS 64            // per warp-ticket (32 threads x 2 rows)
#define NCHUNK (NBATCH / CHUNK_ROWS)   // 4096 row chunks (per column half)

typedef unsigned long long u64;

__device__ unsigned int g_tickets[2];

__global__ void reset_ticket_kernel() { g_tickets[0] = 0u; g_tickets[1] = 0u; }

__device__ __forceinline__ u64 pk2(float lo, float hi) {
    u64 r; asm("mov.b64 %0, {%1, %2};" : "=l"(r) : "f"(lo), "f"(hi)); return r;
}
__device__ __forceinline__ void upk2(u64 v, float& lo, float& hi) {
    asm("mov.b64 {%0, %1}, %2;" : "=f"(lo), "=f"(hi) : "l"(v));
}
__device__ __forceinline__ float lo2(u64 v) { float a, b; upk2(v, a, b); return a; }
__device__ __forceinline__ float hi2(u64 v) { float a, b; upk2(v, a, b); return b; }
__device__ __forceinline__ u64 dup_lo(u64 v) { float a = lo2(v); return pk2(a, a); }
__device__ __forceinline__ u64 dup_hi(u64 v) { float a = hi2(v); return pk2(a, a); }

__device__ __forceinline__ u64 f2fma(u64 a, u64 b, u64 c) {
    u64 d; asm("fma.rn.f32x2 %0, %1, %2, %3;" : "=l"(d) : "l"(a), "l"(b), "l"(c)); return d;
}
__device__ __forceinline__ u64 f2mul(u64 a, u64 b) {
    u64 d; asm("mul.rn.f32x2 %0, %1, %2;" : "=l"(d) : "l"(a), "l"(b)); return d;
}

// Per-CTA smem: 8 columns of W for all 969 rows, row stride 32B.
#define SMEM_BYTES (NPOLY * 8 * 4)    // 31,008 B

__global__ void __launch_bounds__(BLOCK, 3)
taylor_kernel(const float* __restrict__ x, const float* __restrict__ W,
              float* __restrict__ out)
{
    extern __shared__ unsigned char smem_raw[];
    float* sW = reinterpret_cast<float*>(smem_raw);   // [969][8]

    const int tid  = threadIdx.x;
    const int half = (int)blockIdx.x & 1;             // cols [8*half, 8*half+8)

    // Cooperative load of this CTA's 8 W columns; fold identity residual:
    // out = x + poly@W  ==  poly@W'  with  W'[1+i][i] += 1.
    #pragma unroll 1
    for (int e = tid; e < NPOLY * 8; e += BLOCK) {
        int row = e >> 3, c = e & 7;
        int col = 8 * half + c;
        float w = W[row * NF + col];
        if (row - 1 == col) w += 1.0f;
        sW[e] = w;
    }
    __syncthreads();

    const int lane = tid & 31;
    const char* wbase = reinterpret_cast<const char*>(sW);
    const long long colbase = 8 * half;

    for (;;) {
        // ---- warp grabs a 64-row chunk ticket (per column half) ----
        unsigned int t;
        if (lane == 0) t = atomicAdd(&g_tickets[half], 1u);
        t = __shfl_sync(0xffffffffu, t, 0);
        if (t >= NCHUNK) break;

        const long long r0 = (long long)t * CHUNK_ROWS + lane * 2;  // rows r0, r0+1

        // ---- load 2 rows of x, pack as row-pairs ----
        const float4* xv = reinterpret_cast<const float4*>(x + r0 * NF);
        u64 xx[NF];
        #pragma unroll
        for (int q = 0; q < 4; q++) {
            float4 a = xv[q];        // row 0
            float4 b = xv[4 + q];    // row 1
            xx[q * 4 + 0] = pk2(a.x, b.x);
            xx[q * 4 + 1] = pk2(a.y, b.y);
            xx[q * 4 + 2] = pk2(a.z, b.z);
            xx[q * 4 + 3] = pk2(a.w, b.w);
        }

        // ---- acc[r*4 + c] = output cols (colbase+2c, +2c+1) of row r ----
        u64 acc[8];
        {   // degree-0 init: acc = W'[0][cols] (identity lives in deg-1 rows)
            const ulonglong2* wp = reinterpret_cast<const ulonglong2*>(wbase);
            ulonglong2 w0 = wp[0], w1 = wp[1];
            acc[0] = w0.x; acc[1] = w0.y; acc[2] = w1.x; acc[3] = w1.y;
            acc[4] = w0.x; acc[5] = w0.y; acc[6] = w1.x; acc[7] = w1.y;
        }

        // Apply feature row ridx with packed monomial m01 = {m_row0, m_row1}
        #define APPLY(ridx, m01) do {                                           \
            const ulonglong2* wp =                                              \
                reinterpret_cast<const ulonglong2*>(wbase + (ridx) * 32);       \
            ulonglong2 w0 = wp[0], w1 = wp[1];                                  \
            u64 d0 = dup_lo(m01), d1 = dup_hi(m01);                             \
            acc[0] = f2fma(d0, w0.x, acc[0]); acc[1] = f2fma(d0, w0.y, acc[1]); \
            acc[2] = f2fma(d0, w1.x, acc[2]); acc[3] = f2fma(d0, w1.y, acc[3]); \
            acc[4] = f2fma(d1, w0.x, acc[4]); acc[5] = f2fma(d1, w0.y, acc[5]); \
            acc[6] = f2fma(d1, w1.x, acc[6]); acc[7] = f2fma(d1, w1.y, acc[7]); \
        } while (0)

        // degree 1 (identity already folded into W')
        #pragma unroll
        for (int i = 0; i < NF; i++) APPLY(1 + i, xx[i]);

        // degree 2 & 3 fused: p = x_a*x_b (a>=b); q = x_i*p (i>=a)
        #pragma unroll
        for (int ia = 0; ia < NF; ia++) {
            #pragma unroll
            for (int ib = 0; ib <= ia; ib++) {
                u64 p = f2mul(xx[ia], xx[ib]);
                APPLY(17 + (ia * (ia + 1)) / 2 + ib, p);
                #pragma unroll
                for (int ii = ia; ii < NF; ii++) {
                    u64 q = f2mul(xx[ii], p);
                    const int row3 = 153 + (ii * (ii + 1) * (ii + 2)) / 6
                                   + (ia * (ia + 1)) / 2 + ib;
                    APPLY(row3, q);
                }
            }
        }
        #undef APPLY

        // ---- store 2 rows x 8 cols ----
        {
            ulonglong2 s0; s0.x = acc[0]; s0.y = acc[1];
            ulonglong2 s1; s1.x = acc[2]; s1.y = acc[3];
            ulonglong2* op0 =
                reinterpret_cast<ulonglong2*>(out + r0 * NF + colbase);
            op0[0] = s0; op0[1] = s1;
            ulonglong2 s2; s2.x = acc[4]; s2.y = acc[5];
            ulonglong2 s3; s3.x = acc[6]; s3.y = acc[7];
            ulonglong2* op1 =
                reinterpret_cast<ulonglong2*>(out + (r0 + 1) * NF + colbase);
            op1[0] = s2; op1[1] = s3;
        }
    }
}

extern "C" void kernel_launch(void* const* d_in, const int* in_sizes, int n_in,
                              void* d_out, int out_size)
{
    const float* x = (const float*)d_in[0];   // [262144, 16]
    const float* W = (const float*)d_in[1];   // [969, 16]
    float* out = (float*)d_out;

    cudaFuncSetAttribute(taylor_kernel,
                         cudaFuncAttributeMaxDynamicSharedMemorySize,
                         SMEM_BYTES);

    reset_ticket_kernel<<<1, 1>>>();
    taylor_kernel<<<GRID, BLOCK, SMEM_BYTES>>>(x, W, out);
}